// round 16
// baseline (speedup 1.0000x reference)
#include <cuda_runtime.h>
#include <cuda_bf16.h>
#include <math.h>
#include <stdint.h>

#define NN 50000
#define NPAD 50048              // 391 * 128
#define NE 500000
#define EPS_BN 1e-5f
#define SNORM 0.0044721359549995794f   // 1/sqrt(50000)
#define DELTA_F 2.5f
#define NTILES 391

// ======================= helpers =======================
__device__ __forceinline__ uint32_t smem_u32(const void* p) {
    uint32_t a;
    asm("{ .reg .u64 t; cvta.to.shared.u64 t, %1; cvt.u32.u64 %0, t; }" : "=r"(a) : "l"(p));
    return a;
}
__device__ __forceinline__ void ldsm4(uint32_t a[4], uint32_t addr) {
    asm volatile("ldmatrix.sync.aligned.m8n8.x4.shared.b16 {%0,%1,%2,%3}, [%4];"
                 : "=r"(a[0]), "=r"(a[1]), "=r"(a[2]), "=r"(a[3]) : "r"(addr));
}
__device__ __forceinline__ void ldsm4t(uint32_t a[4], uint32_t addr) {
    asm volatile("ldmatrix.sync.aligned.m8n8.x4.trans.shared.b16 {%0,%1,%2,%3}, [%4];"
                 : "=r"(a[0]), "=r"(a[1]), "=r"(a[2]), "=r"(a[3]) : "r"(addr));
}
__device__ __forceinline__ void mma16816(float* c, const uint32_t a[4],
                                         uint32_t b0, uint32_t b1) {
    asm volatile("mma.sync.aligned.m16n8k16.row.col.f32.bf16.bf16.f32 "
        "{%0,%1,%2,%3}, {%4,%5,%6,%7}, {%8,%9}, {%0,%1,%2,%3};"
        : "+f"(c[0]), "+f"(c[1]), "+f"(c[2]), "+f"(c[3])
        : "r"(a[0]), "r"(a[1]), "r"(a[2]), "r"(a[3]), "r"(b0), "r"(b1));
}
#define CP16(dst, src) \
    asm volatile("cp.async.cg.shared.global [%0], [%1], 16;" :: "r"(dst), "l"(src))
#define CP_COMMIT() asm volatile("cp.async.commit_group;")
#define CP_WAIT(n)  asm volatile("cp.async.wait_group %0;" :: "n"(n))

__device__ __forceinline__ void split_pack(float v0, float v1, uint32_t& uh, uint32_t& ul) {
    __nv_bfloat162 hp, lp;
    hp.x = __float2bfloat16(v0); hp.y = __float2bfloat16(v1);
    lp.x = __float2bfloat16(v0 - __bfloat162float(hp.x));
    lp.y = __float2bfloat16(v1 - __bfloat162float(hp.y));
    uh = *(uint32_t*)&hp; ul = *(uint32_t*)&lp;
}

// ======================= scratch (device globals) =======================
__device__ float g_PQ[(size_t)NPAD * 128];     // [P(64) | Q(64)] per node
__device__ uint32_t g_Xh[(size_t)NPAD * 224];  // X bf16 hi pairs; padded rows stay 0
__device__ uint32_t g_Xl[(size_t)NPAD * 224];
__device__ uint32_t g_hH[(size_t)NPAD * 32];   // h bf16 hi pairs
__device__ uint32_t g_hL[(size_t)NPAD * 32];
__device__ uint32_t g_huH[(size_t)NPAD * 32];  // hu bf16 hi pairs
__device__ uint32_t g_huL[(size_t)NPAD * 32];
__device__ float g_ot[(size_t)NN * 64];
__device__ float g_hA[(size_t)NN * 64];
__device__ float g_hB[(size_t)NN * 64];
__device__ float g_scal[(size_t)NPAD * 2];     // amp, att (padded rows stay 0)
__device__ int   g_deg[NN];
__device__ int   g_rowptr[NN + 1];
__device__ int   g_cursor[NN];
__device__ int   g_srcsorted[NE];
__device__ uint32_t g_BzKh[4 * 448 * 96];      // per-layer Bz bf16 hi, K-major pairs
__device__ uint32_t g_BzKl[4 * 448 * 96];
__device__ uint32_t g_BpqKh[4 * 64 * 64];
__device__ uint32_t g_BpqKl[4 * 64 * 64];
__device__ float g_stats[1024];                // [layer][BN1 s, BN1 q, BN2 s, BN2 q] x 64

// ======================= CSR build =======================
__global__ void hist_kernel(const int* __restrict__ dst) {
    int e = blockIdx.x * blockDim.x + threadIdx.x;
    if (e < NE) atomicAdd(&g_deg[dst[e]], 1);
}
__global__ void scan_kernel() {
    int tid = threadIdx.x;
    int base = tid * 49;
    int sum = 0;
    for (int j = 0; j < 49; j++) {
        int i = base + j;
        if (i < NN) sum += g_deg[i];
    }
    int lane = tid & 31, wid = tid >> 5;
    int v = sum;
#pragma unroll
    for (int o = 1; o < 32; o <<= 1) {
        int t = __shfl_up_sync(0xFFFFFFFFu, v, o);
        if (lane >= o) v += t;
    }
    __shared__ int wsum[32];
    if (lane == 31) wsum[wid] = v;
    __syncthreads();
    if (wid == 0) {
        int x = wsum[lane];
#pragma unroll
        for (int o = 1; o < 32; o <<= 1) {
            int t = __shfl_up_sync(0xFFFFFFFFu, x, o);
            if (lane >= o) x += t;
        }
        wsum[lane] = x;
    }
    __syncthreads();
    int excl = v - sum + (wid > 0 ? wsum[wid - 1] : 0);
    int run = excl;
    for (int j = 0; j < 49; j++) {
        int i = base + j;
        if (i < NN) {
            int d = g_deg[i];
            g_cursor[i] = run;
            run += d;
            g_rowptr[i + 1] = run;
        }
    }
    if (tid == 0) g_rowptr[0] = 0;
}
__global__ void scatter_kernel(const int* __restrict__ src, const int* __restrict__ dst) {
    int e = blockIdx.x * blockDim.x + threadIdx.x;
    if (e < NE) {
        int p = atomicAdd(&g_cursor[dst[e]], 1);
        g_srcsorted[p] = src[e];
    }
}

// ======================= one-shot prepack =======================
__global__ void prepack_all_kernel(const float* __restrict__ WM, const float* __restrict__ WU) {
    int idx = blockIdx.x * 256 + threadIdx.x;
    if (idx < 172032) {                          // Bz: 4 layers x 448 x 96 pairs
        int lyr = idx / 43008, r = idx - lyr * 43008;
        int k = r / 96, n2 = r - k * 96;
        const float* W = WU + (size_t)lyr * 1216 * 64;
        float v[2];
#pragma unroll
        for (int j = 0; j < 2; j++) {
            int n = n2 * 2 + j;
            float val;
            if (k < 384) {
                int b = n >> 6;
                int wrow = ((b == 0) ? 64 : (b == 1) ? 448 : 832) + k;
                val = W[wrow * 64 + (n & 63)];
            } else {
                val = (n < 64) ? W[(k - 384) * 64 + n] : 0.f;
            }
            v[j] = val;
        }
        uint32_t uh, ul; split_pack(v[0], v[1], uh, ul);
        g_BzKh[idx] = uh; g_BzKl[idx] = ul;
    } else if (idx < 188416) {                   // Bpq: 4 layers x 64 x 64 pairs
        int j0 = idx - 172032;
        int lyr = j0 >> 12, r = j0 & 4095;
        int k = r >> 6, n2 = r & 63;
        const float* W = WM + (size_t)lyr * 128 * 64;
        float v[2];
#pragma unroll
        for (int j = 0; j < 2; j++) {
            int n = n2 * 2 + j;
            v[j] = (n < 64) ? W[k * 64 + n] : W[(64 + k) * 64 + (n - 64)];
        }
        uint32_t uh, ul; split_pack(v[0], v[1], uh, ul);
        g_BpqKh[j0] = uh; g_BpqKl[j0] = ul;
    } else if (idx < 189440) {
        g_stats[idx - 188416] = 0.f;
    } else if (idx < 239440) {
        g_deg[idx - 189440] = 0;
    }
}

// ======================= PQ MMA (+ fused BN2/relu/residual of previous layer) ============
#define PS_AH 0
#define PS_AL 18432
#define PS_BH 36864
#define PS_BL 54272
#define PS_CONST 71680
#define P_SMEM 72192

__global__ __launch_bounds__(256, 3) void pqmma_kernel(
    const float* __restrict__ srcO, const float* __restrict__ hprev,
    const float* __restrict__ go, const float* __restrict__ bo,
    float* __restrict__ h_out, int statsL, int bsliceL, int mode)
{
    extern __shared__ char dsm[];
    uint32_t sb = smem_u32(dsm);
    int tid = threadIdx.x, w = tid >> 5, l = tid & 31, g = l >> 2, t = l & 3;
    int tB = blockIdx.x * 128;

    const uint32_t* BKh = g_BpqKh + (size_t)bsliceL * 4096;
    const uint32_t* BKl = g_BpqKl + (size_t)bsliceL * 4096;
    for (int i = tid; i < 1024; i += 256) {
        int kr = i >> 4, j = i & 15;
        uint32_t d = (uint32_t)(kr * 272 + j * 16);
        CP16(sb + PS_BH + d, BKh + kr * 64 + j * 4);
        CP16(sb + PS_BL + d, BKl + kr * 64 + j * 4);
    }
    CP_COMMIT();

    float* cst = (float*)(dsm + PS_CONST);
    if (mode && tid < 64) {
        float mu  = g_stats[statsL * 256 + 128 + tid] * (1.f / NN);
        float var = g_stats[statsL * 256 + 192 + tid] * (1.f / NN) - mu * mu;
        float iv  = rsqrtf(fmaxf(var, 0.f) + EPS_BN);
        float s2  = iv * go[tid];
        cst[tid] = s2;
        cst[64 + tid] = bo[tid] - mu * s2;
    }
    __syncthreads();

    for (int i = tid; i < 2048; i += 256) {
        int row = i >> 4, c4 = (i & 15) * 4, gr = tB + row;
        float4 v = make_float4(0.f, 0.f, 0.f, 0.f);
        if (gr < NN) {
            float4 o = *(const float4*)(srcO + (size_t)gr * 64 + c4);
            if (mode) {
                float4 hp = *(const float4*)(hprev + (size_t)gr * 64 + c4);
                v.x = fmaxf(o.x * cst[c4 + 0] + cst[64 + c4 + 0], 0.f) + hp.x;
                v.y = fmaxf(o.y * cst[c4 + 1] + cst[64 + c4 + 1], 0.f) + hp.y;
                v.z = fmaxf(o.z * cst[c4 + 2] + cst[64 + c4 + 2], 0.f) + hp.z;
                v.w = fmaxf(o.w * cst[c4 + 3] + cst[64 + c4 + 3], 0.f) + hp.w;
                *(float4*)(h_out + (size_t)gr * 64 + c4) = v;
            } else {
                v = o;
            }
        }
        uint32_t uh0, ul0, uh1, ul1;
        split_pack(v.x, v.y, uh0, ul0);
        split_pack(v.z, v.w, uh1, ul1);
        int pi = gr * 32 + (c4 >> 1);
        *(uint2*)(g_hH + pi) = make_uint2(uh0, uh1);
        *(uint2*)(g_hL + pi) = make_uint2(ul0, ul1);
        uint32_t soff = (uint32_t)(row * 144 + c4 * 2);
        *(uint2*)(dsm + PS_AH + soff) = make_uint2(uh0, uh1);
        *(uint2*)(dsm + PS_AL + soff) = make_uint2(ul0, ul1);
    }
    CP_WAIT(0);
    __syncthreads();

    float c[64];
#pragma unroll
    for (int i = 0; i < 64; i++) c[i] = 0.f;

    uint32_t aAoff = (uint32_t)(w * 16 + (l & 15)) * 144 + (uint32_t)(l >> 4) * 16;
    uint32_t aBoff = (uint32_t)(l & 15) * 272 + (uint32_t)(l >> 4) * 16;
    uint32_t aAh = sb + PS_AH + aAoff, aAl = sb + PS_AL + aAoff;
    uint32_t aBh = sb + PS_BH + aBoff, aBl = sb + PS_BL + aBoff;
#pragma unroll
    for (int ks = 0; ks < 4; ks++) {
        uint32_t ah[4], al[4];
        ldsm4(ah, aAh + ks * 32);
        ldsm4(al, aAl + ks * 32);
#pragma unroll
        for (int nn = 0; nn < 8; nn++) {
            uint32_t bh[4], bl[4];
            ldsm4t(bh, aBh + ks * 16 * 272 + nn * 32);
            ldsm4t(bl, aBl + ks * 16 * 272 + nn * 32);
            mma16816(c + nn * 8,     ah, bh[0], bh[1]);
            mma16816(c + nn * 8 + 4, ah, bh[2], bh[3]);
            mma16816(c + nn * 8,     ah, bl[0], bl[1]);
            mma16816(c + nn * 8 + 4, ah, bl[2], bl[3]);
            mma16816(c + nn * 8,     al, bh[0], bh[1]);
            mma16816(c + nn * 8 + 4, al, bh[2], bh[3]);
        }
    }
    __syncthreads();

    float* stage = (float*)dsm;
    int r0 = w * 16 + g, r1 = r0 + 8;
#pragma unroll
    for (int jj = 0; jj < 16; jj++) {
        int col = jj * 8 + 2 * t;
        stage[r0 * 132 + col]     = c[jj * 4 + 0];
        stage[r0 * 132 + col + 1] = c[jj * 4 + 1];
        stage[r1 * 132 + col]     = c[jj * 4 + 2];
        stage[r1 * 132 + col + 1] = c[jj * 4 + 3];
    }
    __syncthreads();
    for (int i = tid; i < 4096; i += 256) {
        int row = i >> 5, c4 = (i & 31) * 4;
        float4 v = make_float4(stage[row * 132 + c4],     stage[row * 132 + c4 + 1],
                               stage[row * 132 + c4 + 2], stage[row * 132 + c4 + 3]);
        *(float4*)(g_PQ + (size_t)(tB + row) * 128 + c4) = v;
    }
}

// ======================= aggregation -> packed bf16 X (one warp per node) ================
__global__ __launch_bounds__(256) void agg_kernel(const float* __restrict__ bM)
{
    int v = blockIdx.x * 8 + (threadIdx.x >> 5);
    int lane = threadIdx.x & 31;
    if (v >= NN) return;
    int beg = g_rowptr[v], end = g_rowptr[v + 1];
    int c0 = 2 * lane;
    const float* qrow = g_PQ + (size_t)v * 128 + 64;
    float2 qv = *(const float2*)(qrow + c0);
    float2 bv = *(const float2*)(bM + c0);
    float base0 = qv.x + bv.x;
    float base1 = qv.y + bv.y;
    float s0 = 0.f, s1 = 0.f, q0 = 0.f, q1 = 0.f;
    float mx0 = -INFINITY, mx1 = -INFINITY, mn0 = INFINITY, mn1 = INFINITY;
#pragma unroll 4
    for (int p = beg; p < end; p++) {
        int s = g_srcsorted[p];
        float2 pv = *(const float2*)(g_PQ + (size_t)s * 128 + c0);
        float m0 = pv.x + base0;
        float m1 = pv.y + base1;
        s0 += m0; q0 += m0 * m0; mx0 = fmaxf(mx0, m0); mn0 = fminf(mn0, m0);
        s1 += m1; q1 += m1 * m1; mx1 = fmaxf(mx1, m1); mn1 = fminf(mn1, m1);
    }
    float deg = (float)(end - beg);
    float denom = fmaxf(deg, 1.f);
    float inv = 1.f / denom;
    float mean0 = s0 * inv, mean1 = s1 * inv;
    float var0 = fmaxf(q0 * inv - mean0 * mean0, 0.f);
    float var1 = fmaxf(q1 * inv - mean1 * mean1, 0.f);
    float std0 = sqrtf(var0 + 1e-30f);
    float std1 = sqrtf(var1 + 1e-30f);
    if (end == beg) { mx0 = mx1 = 0.f; mn0 = mn1 = 0.f; }
    uint32_t* xh = g_Xh + (size_t)v * 224;
    uint32_t* xl = g_Xl + (size_t)v * 224;
    uint32_t uh, ul;
    split_pack(mean0, mean1, uh, ul); xh[lane] = uh;        xl[lane] = ul;
    split_pack(mx0, mx1, uh, ul);     xh[32 + lane] = uh;   xl[32 + lane] = ul;
    split_pack(mn0, mn1, uh, ul);     xh[64 + lane] = uh;   xl[64 + lane] = ul;
    split_pack(std0, std1, uh, ul);   xh[96 + lane] = uh;   xl[96 + lane] = ul;
    split_pack(var0, var1, uh, ul);   xh[128 + lane] = uh;  xl[128 + lane] = ul;
    split_pack(s0, s1, uh, ul);       xh[160 + lane] = uh;  xl[160 + lane] = ul;
    xh[192 + lane] = g_hH[(size_t)v * 32 + lane];
    xl[192 + lane] = g_hL[(size_t)v * 32 + lane];
    if (lane == 0) {
        float logD = logf(deg + 1.f);
        g_scal[2 * v]     = logD * (1.f / DELTA_F);
        g_scal[2 * v + 1] = (logD > 0.f) ? (DELTA_F / logD) : 0.f;
    }
}

// ======================= Z MMA (512 thr, 16 warps: 8 rowgrp x 2 colhalf) =================
// warp (rw, cw): rows rw*16..+16, cols {cw*32..+32} of each of Z0/Z1/Z2 (thread-local combine)
#define ZS_AH 0
#define ZS_AL 18432
#define ZS_BH 36864
#define ZS_BL 62464
#define Z_STAGE 88064
#define ZS_BU (2 * Z_STAGE)
#define Z_SMEM (2 * Z_STAGE + 256)

__global__ __launch_bounds__(512, 1) void zmma_kernel(const float* __restrict__ bU, int layer)
{
    extern __shared__ char dsm[];
    uint32_t sb = smem_u32(dsm);
    int tid = threadIdx.x, w = tid >> 5, l = tid & 31, g = l >> 2, t = l & 3;
    int rw = w & 7, cw = w >> 3;
    int tB = blockIdx.x * 128;
    if (tid < 64) ((float*)(dsm + ZS_BU))[tid] = bU[tid];

    const uint32_t* BzH = g_BzKh + (size_t)layer * 43008;
    const uint32_t* BzL = g_BzKl + (size_t)layer * 43008;

    float c[48];        // [(s*2+nn)*8 + sub*4 + j], s in 0..2 (Z seg), nn in 0..1 (16-col grp)
#pragma unroll
    for (int i = 0; i < 48; i++) c[i] = 0.f;

    uint32_t aAoff = (uint32_t)(rw * 16 + (l & 15)) * 144 + (uint32_t)(l >> 4) * 16;
    uint32_t aBoff = (uint32_t)(l & 15) * 400 + (uint32_t)(l >> 4) * 16 + (uint32_t)cw * 64;

    // prefetch chunk 0
    {
        uint32_t bs = sb;
        for (int i = tid; i < 1024; i += 512) {
            int r = i >> 3, j = i & 7;
            uint32_t d = (uint32_t)(r * 144 + j * 16);
            CP16(bs + ZS_AH + d, g_Xh + (size_t)(tB + r) * 224 + j * 4);
            CP16(bs + ZS_AL + d, g_Xl + (size_t)(tB + r) * 224 + j * 4);
        }
        for (int i = tid; i < 1536; i += 512) {
            int kr = i / 24, j = i - kr * 24;
            uint32_t d = (uint32_t)(kr * 400 + j * 16);
            CP16(bs + ZS_BH + d, BzH + kr * 96 + j * 4);
            CP16(bs + ZS_BL + d, BzL + kr * 96 + j * 4);
        }
        CP_COMMIT();
    }

    for (int ch = 0; ch < 7; ch++) {
        if (ch < 6) {
            uint32_t bs = sb + ((ch + 1) & 1) * Z_STAGE;
            int kc = (ch + 1) * 32;
            const uint32_t* Bh = BzH + (size_t)(ch + 1) * 6144;
            const uint32_t* Bl = BzL + (size_t)(ch + 1) * 6144;
            for (int i = tid; i < 1024; i += 512) {
                int r = i >> 3, j = i & 7;
                uint32_t d = (uint32_t)(r * 144 + j * 16);
                CP16(bs + ZS_AH + d, g_Xh + (size_t)(tB + r) * 224 + kc + j * 4);
                CP16(bs + ZS_AL + d, g_Xl + (size_t)(tB + r) * 224 + kc + j * 4);
            }
            for (int i = tid; i < 1536; i += 512) {
                int kr = i / 24, j = i - kr * 24;
                uint32_t d = (uint32_t)(kr * 400 + j * 16);
                CP16(bs + ZS_BH + d, Bh + kr * 96 + j * 4);
                CP16(bs + ZS_BL + d, Bl + kr * 96 + j * 4);
            }
            CP_COMMIT();
            CP_WAIT(1);
        } else {
            CP_WAIT(0);
        }
        __syncthreads();

        uint32_t bufOff = (ch & 1) * Z_STAGE;
        uint32_t aAh = sb + bufOff + ZS_AH + aAoff, aAl = sb + bufOff + ZS_AL + aAoff;
        uint32_t aBh = sb + bufOff + ZS_BH + aBoff, aBl = sb + bufOff + ZS_BL + aBoff;
#pragma unroll
        for (int ks = 0; ks < 4; ks++) {
            uint32_t ah[4], al[4];
            ldsm4(ah, aAh + ks * 32);
            ldsm4(al, aAl + ks * 32);
#pragma unroll
            for (int s = 0; s < 3; s++) {
#pragma unroll
                for (int nn = 0; nn < 2; nn++) {
                    uint32_t bh[4], bl[4];
                    uint32_t boff = (uint32_t)(ks * 16 * 400 + s * 128 + nn * 32);
                    ldsm4t(bh, aBh + boff);
                    ldsm4t(bl, aBl + boff);
                    float* cc = c + (s * 2 + nn) * 8;
                    mma16816(cc,     ah, bh[0], bh[1]);
                    mma16816(cc + 4, ah, bh[2], bh[3]);
                    mma16816(cc,     ah, bl[0], bl[1]);
                    mma16816(cc + 4, ah, bl[2], bl[3]);
                    mma16816(cc,     al, bh[0], bh[1]);
                    mma16816(cc + 4, al, bh[2], bh[3]);
                }
            }
        }
        __syncthreads();
    }

    // thread-local combine: hu = (Z0 + amp*Z1 + att*Z2 + bU) * SNORM
    int r0 = rw * 16 + g, r1 = r0 + 8;
    int gr0 = tB + r0, gr1 = tB + r1;
    float amp0 = g_scal[2 * gr0], att0 = g_scal[2 * gr0 + 1];
    float amp1 = g_scal[2 * gr1], att1 = g_scal[2 * gr1 + 1];
    const float* buS = (const float*)(dsm + ZS_BU);
    float* stage = (float*)dsm;    // [128][66] = 33792 B, fits in stage-0 A region
#pragma unroll
    for (int nn = 0; nn < 2; nn++) {
#pragma unroll
        for (int sub = 0; sub < 2; sub++) {
            int col = cw * 32 + nn * 16 + sub * 8 + 2 * t;
            int b0 = nn * 8 + sub * 4;
            int b1 = (2 + nn) * 8 + sub * 4;
            int b2 = (4 + nn) * 8 + sub * 4;
            float bu0 = buS[col], bu1 = buS[col + 1];
            stage[r0 * 66 + col]     = (c[b0+0] + amp0 * c[b1+0] + att0 * c[b2+0] + bu0) * SNORM;
            stage[r0 * 66 + col + 1] = (c[b0+1] + amp0 * c[b1+1] + att0 * c[b2+1] + bu1) * SNORM;
            stage[r1 * 66 + col]     = (c[b0+2] + amp1 * c[b1+2] + att1 * c[b2+2] + bu0) * SNORM;
            stage[r1 * 66 + col + 1] = (c[b0+3] + amp1 * c[b1+3] + att1 * c[b2+3] + bu1) * SNORM;
        }
    }
    __syncthreads();
    // packed hu store
    for (int i = tid; i < 2048; i += 512) {
        int row = i >> 4, c4 = (i & 15) * 4;
        float4 v = make_float4(stage[row * 66 + c4],     stage[row * 66 + c4 + 1],
                               stage[row * 66 + c4 + 2], stage[row * 66 + c4 + 3]);
        uint32_t uh0, ul0, uh1, ul1;
        split_pack(v.x, v.y, uh0, ul0);
        split_pack(v.z, v.w, uh1, ul1);
        int pi = (tB + row) * 32 + (c4 >> 1);
        *(uint2*)(g_huH + pi) = make_uint2(uh0, uh1);
        *(uint2*)(g_huL + pi) = make_uint2(ul0, ul1);
    }
    // BN1 stats
    {
        int ci = tid & 63, hh = tid >> 6;   // hh in 0..7
        float s = 0.f, q = 0.f;
        for (int r = hh * 16; r < hh * 16 + 16; r++) {
            if (tB + r < NN) { float x = stage[r * 66 + ci]; s += x; q += x * x; }
        }
        atomicAdd(&g_stats[layer * 256 + ci], s);
        atomicAdd(&g_stats[layer * 256 + 64 + ci], q);
    }
}

// ======================= mix MMA: BN1-folded hu @ Wmix + leaky + residual + BN2 stats ====
#define MX_AH 0
#define MX_AL 18432
#define MX_BH 36864
#define MX_BL 46080
#define MX_CONST 55296
#define MX_SMEM 57088

__global__ __launch_bounds__(256) void mix_kernel(
    const float* __restrict__ h_in, const float* __restrict__ Wmix,
    const float* __restrict__ bmix, const float* __restrict__ gt,
    const float* __restrict__ bt, int layer)
{
    extern __shared__ char dsm[];
    uint32_t sb = smem_u32(dsm);
    int tid = threadIdx.x, w = tid >> 5, l = tid & 31, g = l >> 2, t = l & 3;
    int tB = blockIdx.x * 128;

    for (int i = tid; i < 1024; i += 256) {
        int r = i >> 3, j = i & 7;
        uint32_t d = (uint32_t)(r * 144 + j * 16);
        CP16(sb + MX_AH + d, g_huH + (size_t)(tB + r) * 32 + j * 4);
        CP16(sb + MX_AL + d, g_huL + (size_t)(tB + r) * 32 + j * 4);
    }
    CP_COMMIT();

    float* cst = (float*)(dsm + MX_CONST);
    if (tid < 64) {
        float mu  = g_stats[layer * 256 + tid] * (1.f / NN);
        float var = g_stats[layer * 256 + 64 + tid] * (1.f / NN) - mu * mu;
        float iv  = rsqrtf(fmaxf(var, 0.f) + EPS_BN);
        float s   = gt[tid] * iv;
        cst[tid] = s;
        cst[64 + tid] = bt[tid] - mu * s;
    }
    __syncthreads();

    for (int i = tid; i < 2048; i += 256) {
        int k = i >> 5, n2 = i & 31;
        float s = cst[k];
        float2 wv = *(const float2*)(Wmix + k * 64 + n2 * 2);
        uint32_t uh, ul; split_pack(s * wv.x, s * wv.y, uh, ul);
        uint32_t d = (uint32_t)(k * 144 + n2 * 4);
        *(uint32_t*)(dsm + MX_BH + d) = uh;
        *(uint32_t*)(dsm + MX_BL + d) = ul;
    }
    {
        int n = tid & 63, kq = tid >> 6;
        float pb = 0.f;
        for (int k = kq * 16; k < kq * 16 + 16; k++)
            pb += cst[64 + k] * Wmix[k * 64 + n];
        cst[192 + tid] = pb;
    }
    CP_WAIT(0);
    __syncthreads();
    if (tid < 64)
        cst[128 + tid] = bmix[tid] + cst[192 + tid] + cst[256 + tid] + cst[320 + tid] + cst[384 + tid];

    float c[32];
#pragma unroll
    for (int i = 0; i < 32; i++) c[i] = 0.f;

    uint32_t aAoff = (uint32_t)(w * 16 + (l & 15)) * 144 + (uint32_t)(l >> 4) * 16;
    uint32_t aBoff = (uint32_t)(l & 15) * 144 + (uint32_t)(l >> 4) * 16;
    uint32_t aAh = sb + MX_AH + aAoff, aAl = sb + MX_AL + aAoff;
    uint32_t aBh = sb + MX_BH + aBoff, aBl = sb + MX_BL + aBoff;
#pragma unroll
    for (int ks = 0; ks < 4; ks++) {
        uint32_t ah[4], al[4];
        ldsm4(ah, aAh + ks * 32);
        ldsm4(al, aAl + ks * 32);
#pragma unroll
        for (int nn = 0; nn < 4; nn++) {
            uint32_t bh[4], bl[4];
            ldsm4t(bh, aBh + ks * 16 * 144 + nn * 32);
            ldsm4t(bl, aBl + ks * 16 * 144 + nn * 32);
            mma16816(c + nn * 8,     ah, bh[0], bh[1]);
            mma16816(c + nn * 8 + 4, ah, bh[2], bh[3]);
            mma16816(c + nn * 8,     ah, bl[0], bl[1]);
            mma16816(c + nn * 8 + 4, ah, bl[2], bl[3]);
            mma16816(c + nn * 8,     al, bh[0], bh[1]);
            mma16816(c + nn * 8 + 4, al, bh[2], bh[3]);
        }
    }
    __syncthreads();

    float* stage = (float*)dsm;
    int r0 = w * 16 + g, r1 = r0 + 8;
    int gr0 = tB + r0, gr1 = tB + r1;
#pragma unroll
    for (int jj = 0; jj < 8; jj++) {
        int col = jj * 8 + 2 * t;
        float bb0 = cst[128 + col], bb1 = cst[128 + col + 1];
        float a0 = c[jj * 4 + 0] + bb0, a1 = c[jj * 4 + 1] + bb1;
        float a2 = c[jj * 4 + 2] + bb0, a3 = c[jj * 4 + 3] + bb1;
        a0 = (a0 > 0.f) ? a0 : 0.01f * a0;
        a1 = (a1 > 0.f) ? a1 : 0.01f * a1;
        a2 = (a2 > 0.f) ? a2 : 0.01f * a2;
        a3 = (a3 > 0.f) ? a3 : 0.01f * a3;
        float h0 = 0.f, h1 = 0.f, h2 = 0.f, h3 = 0.f;
        if (gr0 < NN) { float2 hv = *(const float2*)(h_in + (size_t)gr0 * 64 + col); h0 = hv.x; h1 = hv.y; }
        if (gr1 < NN) { float2 hv = *(const float2*)(h_in + (size_t)gr1 * 64 + col); h2 = hv.x; h3 = hv.y; }
        stage[r0 * 66 + col]     = a0 + h0;
        stage[r0 * 66 + col + 1] = a1 + h1;
        stage[r1 * 66 + col]     = a2 + h2;
        stage[r1 * 66 + col + 1] = a3 + h3;
    }
    __syncthreads();
    for (int i = tid; i < 2048; i += 256) {
        int row = i >> 4, c4 = (i & 15) * 4;
        int gr = tB + row;
        if (gr < NN) {
            float4 v = make_float4(stage[row * 66 + c4],     stage[row * 66 + c4 + 1],
                                   stage[row * 66 + c4 + 2], stage[row * 66 + c4 + 3]);
            *(float4*)(g_ot + (size_t)gr * 64 + c4) = v;
        }
    }
    {
        int ci = tid & 63, hh = tid >> 6;
        float s = 0.f, q = 0.f;
        for (int r = hh * 32; r < hh * 32 + 32; r++) {
            if (tB + r < NN) { float x = stage[r * 66 + ci]; s += x; q += x * x; }
        }
        atomicAdd(&g_stats[layer * 256 + 128 + ci], s);
        atomicAdd(&g_stats[layer * 256 + 192 + ci], q);
    }
}

// ======================= final (layer 3): BN2 + relu + residual -> d_out =================
__global__ void final_kernel(const float* __restrict__ h_in,
                             const float* __restrict__ go,
                             const float* __restrict__ bo,
                             float* __restrict__ h_out, int layer)
{
    int i = blockIdx.x * blockDim.x + threadIdx.x;
    if (i >= NN * 32) return;
    int p = i & 31;
    int c0 = 2 * p;
    float mu0  = g_stats[layer * 256 + 128 + c0] * (1.f / NN);
    float mu1  = g_stats[layer * 256 + 128 + c0 + 1] * (1.f / NN);
    float var0 = g_stats[layer * 256 + 192 + c0] * (1.f / NN) - mu0 * mu0;
    float var1 = g_stats[layer * 256 + 192 + c0 + 1] * (1.f / NN) - mu1 * mu1;
    float iv0  = rsqrtf(fmaxf(var0, 0.f) + EPS_BN);
    float iv1  = rsqrtf(fmaxf(var1, 0.f) + EPS_BN);
    float2 ot = *(const float2*)(g_ot + (size_t)i * 2);
    float2 hi = *(const float2*)(h_in + (size_t)i * 2);
    float v0 = fmaxf((ot.x - mu0) * iv0 * go[c0]     + bo[c0],     0.f) + hi.x;
    float v1 = fmaxf((ot.y - mu1) * iv1 * go[c0 + 1] + bo[c0 + 1], 0.f) + hi.y;
    *(float2*)(h_out + (size_t)i * 2) = make_float2(v0, v1);
}

// ======================= host =======================
extern "C" void kernel_launch(void* const* d_in, const int* in_sizes, int n_in,
                              void* d_out, int out_size)
{
    (void)in_sizes; (void)n_in; (void)out_size;
    const float* node_feat = (const float*)d_in[0];
    const int*   esrc = (const int*)d_in[2];
    const int*   edst = (const int*)d_in[3];
    const float* WM   = (const float*)d_in[4];
    const float* bM   = (const float*)d_in[5];
    const float* WU   = (const float*)d_in[6];
    const float* bU   = (const float*)d_in[7];
    const float* gt   = (const float*)d_in[8];
    const float* bt   = (const float*)d_in[9];
    const float* Wmix = (const float*)d_in[10];
    const float* bmix = (const float*)d_in[11];
    const float* go   = (const float*)d_in[12];
    const float* bo   = (const float*)d_in[13];
    float* out = (float*)d_out;

    cudaFuncSetAttribute(zmma_kernel, cudaFuncAttributeMaxDynamicSharedMemorySize, Z_SMEM);
    cudaFuncSetAttribute(pqmma_kernel, cudaFuncAttributeMaxDynamicSharedMemorySize, P_SMEM);
    cudaFuncSetAttribute(mix_kernel, cudaFuncAttributeMaxDynamicSharedMemorySize, MX_SMEM);

    float *phA, *phB, *pot;
    cudaGetSymbolAddress((void**)&phA, g_hA);
    cudaGetSymbolAddress((void**)&phB, g_hB);
    cudaGetSymbolAddress((void**)&pot, g_ot);

    // setup: prepack + CSR build; pqmma L0 slotted before scatter (no CSR dep)
    prepack_all_kernel<<<936, 256>>>(WM, WU);
    hist_kernel<<<(NE + 255) / 256, 256>>>(edst);
    scan_kernel<<<1, 1024>>>();
    pqmma_kernel<<<NTILES, 256, P_SMEM>>>(node_feat, node_feat, go, bo, phA, 0, 0, 0);
    scatter_kernel<<<(NE + 255) / 256, 256>>>(esrc, edst);

    // h chain: h0=node_feat, h1=phA, h2=phB, h3=phA
    const float* hptr[4] = { node_feat, phA, phB, phA };

    for (int lyr = 0; lyr < 4; lyr++) {
        if (lyr > 0)
            pqmma_kernel<<<NTILES, 256, P_SMEM>>>(pot, hptr[lyr - 1],
                                                  go + (lyr - 1) * 64, bo + (lyr - 1) * 64,
                                                  (float*)hptr[lyr], lyr - 1, lyr, 1);
        agg_kernel<<<(NN + 7) / 8, 256>>>(bM + lyr * 64);
        zmma_kernel<<<NTILES, 512, Z_SMEM>>>(bU + lyr * 64, lyr);
        mix_kernel<<<NTILES, 256, MX_SMEM>>>(hptr[lyr], Wmix + (size_t)lyr * 4096,
                                             bmix + lyr * 64, gt + lyr * 64,
                                             bt + lyr * 64, lyr);
    }
    final_kernel<<<(NN * 32 + 255) / 256, 256>>>(hptr[3], go + 3 * 64, bo + 3 * 64, out, 3);
}

// round 17
// speedup vs baseline: 1.2211x; 1.2211x over previous
#include <cuda_runtime.h>
#include <cuda_bf16.h>
#include <cuda_fp16.h>
#include <math.h>
#include <stdint.h>

#define NN 50000
#define NPAD 50048              // 391 * 128
#define NE 500000
#define EPS_BN 1e-5f
#define SNORM 0.0044721359549995794f   // 1/sqrt(50000)
#define DELTA_F 2.5f
#define NTILES 391

// ======================= helpers =======================
__device__ __forceinline__ uint32_t smem_u32(const void* p) {
    uint32_t a;
    asm("{ .reg .u64 t; cvta.to.shared.u64 t, %1; cvt.u32.u64 %0, t; }" : "=r"(a) : "l"(p));
    return a;
}
__device__ __forceinline__ void ldsm4(uint32_t a[4], uint32_t addr) {
    asm volatile("ldmatrix.sync.aligned.m8n8.x4.shared.b16 {%0,%1,%2,%3}, [%4];"
                 : "=r"(a[0]), "=r"(a[1]), "=r"(a[2]), "=r"(a[3]) : "r"(addr));
}
__device__ __forceinline__ void ldsm4t(uint32_t a[4], uint32_t addr) {
    asm volatile("ldmatrix.sync.aligned.m8n8.x4.trans.shared.b16 {%0,%1,%2,%3}, [%4];"
                 : "=r"(a[0]), "=r"(a[1]), "=r"(a[2]), "=r"(a[3]) : "r"(addr));
}
__device__ __forceinline__ void mma16816(float* c, const uint32_t a[4],
                                         uint32_t b0, uint32_t b1) {
    asm volatile("mma.sync.aligned.m16n8k16.row.col.f32.bf16.bf16.f32 "
        "{%0,%1,%2,%3}, {%4,%5,%6,%7}, {%8,%9}, {%0,%1,%2,%3};"
        : "+f"(c[0]), "+f"(c[1]), "+f"(c[2]), "+f"(c[3])
        : "r"(a[0]), "r"(a[1]), "r"(a[2]), "r"(a[3]), "r"(b0), "r"(b1));
}
__device__ __forceinline__ void mma16816h(float* c, const uint32_t a[4],
                                          uint32_t b0, uint32_t b1) {
    asm volatile("mma.sync.aligned.m16n8k16.row.col.f32.f16.f16.f32 "
        "{%0,%1,%2,%3}, {%4,%5,%6,%7}, {%8,%9}, {%0,%1,%2,%3};"
        : "+f"(c[0]), "+f"(c[1]), "+f"(c[2]), "+f"(c[3])
        : "r"(a[0]), "r"(a[1]), "r"(a[2]), "r"(a[3]), "r"(b0), "r"(b1));
}
#define CP16(dst, src) \
    asm volatile("cp.async.cg.shared.global [%0], [%1], 16;" :: "r"(dst), "l"(src))
#define CP_COMMIT() asm volatile("cp.async.commit_group;")
#define CP_WAIT(n)  asm volatile("cp.async.wait_group %0;" :: "n"(n))

__device__ __forceinline__ void split_pack(float v0, float v1, uint32_t& uh, uint32_t& ul) {
    __nv_bfloat162 hp, lp;
    hp.x = __float2bfloat16(v0); hp.y = __float2bfloat16(v1);
    lp.x = __float2bfloat16(v0 - __bfloat162float(hp.x));
    lp.y = __float2bfloat16(v1 - __bfloat162float(hp.y));
    uh = *(uint32_t*)&hp; ul = *(uint32_t*)&lp;
}
__device__ __forceinline__ void split_pack_h(float v0, float v1, uint32_t& uh, uint32_t& ul) {
    __half2 hp, lp;
    hp.x = __float2half_rn(v0); hp.y = __float2half_rn(v1);
    lp.x = __float2half_rn(v0 - __half2float(hp.x));
    lp.y = __float2half_rn(v1 - __half2float(hp.y));
    uh = *(uint32_t*)&hp; ul = *(uint32_t*)&lp;
}
__device__ __forceinline__ uint32_t pack_h2(float v0, float v1) {
    __half2 h = __floats2half2_rn(v0, v1);
    return *(uint32_t*)&h;
}

// ======================= scratch (device globals) =======================
__device__ float g_PQ[(size_t)NPAD * 128];     // [P(64) | Q(64)] per node
__device__ uint32_t g_Xh[(size_t)NPAD * 224];  // X fp16 pairs; padded rows stay 0
__device__ uint32_t g_hH[(size_t)NPAD * 32];   // h bf16 hi pairs
__device__ uint32_t g_hL[(size_t)NPAD * 32];
__device__ uint32_t g_huH[(size_t)NPAD * 32];  // hu bf16 hi pairs
__device__ uint32_t g_huL[(size_t)NPAD * 32];
__device__ float g_ot[(size_t)NN * 64];
__device__ float g_hA[(size_t)NN * 64];
__device__ float g_hB[(size_t)NN * 64];
__device__ float g_scal[(size_t)NPAD * 2];     // amp, att (padded rows stay 0)
__device__ int   g_deg[NN];
__device__ int   g_rowptr[NN + 1];
__device__ int   g_cursor[NN];
__device__ int   g_srcsorted[NE];
__device__ uint32_t g_BzKh[4 * 448 * 96];      // per-layer Bz fp16 hi, K-major pairs
__device__ uint32_t g_BzKl[4 * 448 * 96];      // fp16 lo
__device__ uint32_t g_BpqKh[4 * 64 * 64];      // Bpq bf16 hi (pqmma stays 3-pass bf16)
__device__ uint32_t g_BpqKl[4 * 64 * 64];
__device__ float g_stats[1024];                // [layer][BN1 s, BN1 q, BN2 s, BN2 q] x 64

// ======================= CSR build =======================
__global__ void hist_kernel(const int* __restrict__ dst) {
    int e = blockIdx.x * blockDim.x + threadIdx.x;
    if (e < NE) atomicAdd(&g_deg[dst[e]], 1);
}
__global__ void scan_kernel() {
    int tid = threadIdx.x;
    int base = tid * 49;
    int sum = 0;
    for (int j = 0; j < 49; j++) {
        int i = base + j;
        if (i < NN) sum += g_deg[i];
    }
    int lane = tid & 31, wid = tid >> 5;
    int v = sum;
#pragma unroll
    for (int o = 1; o < 32; o <<= 1) {
        int t = __shfl_up_sync(0xFFFFFFFFu, v, o);
        if (lane >= o) v += t;
    }
    __shared__ int wsum[32];
    if (lane == 31) wsum[wid] = v;
    __syncthreads();
    if (wid == 0) {
        int x = wsum[lane];
#pragma unroll
        for (int o = 1; o < 32; o <<= 1) {
            int t = __shfl_up_sync(0xFFFFFFFFu, x, o);
            if (lane >= o) x += t;
        }
        wsum[lane] = x;
    }
    __syncthreads();
    int excl = v - sum + (wid > 0 ? wsum[wid - 1] : 0);
    int run = excl;
    for (int j = 0; j < 49; j++) {
        int i = base + j;
        if (i < NN) {
            int d = g_deg[i];
            g_cursor[i] = run;
            run += d;
            g_rowptr[i + 1] = run;
        }
    }
    if (tid == 0) g_rowptr[0] = 0;
}
__global__ void scatter_kernel(const int* __restrict__ src, const int* __restrict__ dst) {
    int e = blockIdx.x * blockDim.x + threadIdx.x;
    if (e < NE) {
        int p = atomicAdd(&g_cursor[dst[e]], 1);
        g_srcsorted[p] = src[e];
    }
}

// ======================= one-shot prepack =======================
__global__ void prepack_all_kernel(const float* __restrict__ WM, const float* __restrict__ WU) {
    int idx = blockIdx.x * 256 + threadIdx.x;
    if (idx < 172032) {                          // Bz: 4 layers x 448 x 96 pairs, fp16 hi/lo
        int lyr = idx / 43008, r = idx - lyr * 43008;
        int k = r / 96, n2 = r - k * 96;
        const float* W = WU + (size_t)lyr * 1216 * 64;
        float v[2];
#pragma unroll
        for (int j = 0; j < 2; j++) {
            int n = n2 * 2 + j;
            float val;
            if (k < 384) {
                int b = n >> 6;
                int wrow = ((b == 0) ? 64 : (b == 1) ? 448 : 832) + k;
                val = W[wrow * 64 + (n & 63)];
            } else {
                val = (n < 64) ? W[(k - 384) * 64 + n] : 0.f;
            }
            v[j] = val;
        }
        uint32_t uh, ul; split_pack_h(v[0], v[1], uh, ul);
        g_BzKh[idx] = uh; g_BzKl[idx] = ul;
    } else if (idx < 188416) {                   // Bpq: 4 layers x 64 x 64 pairs, bf16 hi/lo
        int j0 = idx - 172032;
        int lyr = j0 >> 12, r = j0 & 4095;
        int k = r >> 6, n2 = r & 63;
        const float* W = WM + (size_t)lyr * 128 * 64;
        float v[2];
#pragma unroll
        for (int j = 0; j < 2; j++) {
            int n = n2 * 2 + j;
            v[j] = (n < 64) ? W[k * 64 + n] : W[(64 + k) * 64 + (n - 64)];
        }
        uint32_t uh, ul; split_pack(v[0], v[1], uh, ul);
        g_BpqKh[j0] = uh; g_BpqKl[j0] = ul;
    } else if (idx < 189440) {
        g_stats[idx - 188416] = 0.f;
    } else if (idx < 239440) {
        g_deg[idx - 189440] = 0;
    }
}

// ======================= PQ MMA (+ fused BN2/relu/residual of previous layer) ============
#define PS_AH 0
#define PS_AL 18432
#define PS_BH 36864
#define PS_BL 54272
#define PS_CONST 71680
#define P_SMEM 72192

__global__ __launch_bounds__(256, 3) void pqmma_kernel(
    const float* __restrict__ srcO, const float* __restrict__ hprev,
    const float* __restrict__ go, const float* __restrict__ bo,
    float* __restrict__ h_out, int statsL, int bsliceL, int mode)
{
    extern __shared__ char dsm[];
    uint32_t sb = smem_u32(dsm);
    int tid = threadIdx.x, w = tid >> 5, l = tid & 31, g = l >> 2, t = l & 3;
    int tB = blockIdx.x * 128;

    const uint32_t* BKh = g_BpqKh + (size_t)bsliceL * 4096;
    const uint32_t* BKl = g_BpqKl + (size_t)bsliceL * 4096;
    for (int i = tid; i < 1024; i += 256) {
        int kr = i >> 4, j = i & 15;
        uint32_t d = (uint32_t)(kr * 272 + j * 16);
        CP16(sb + PS_BH + d, BKh + kr * 64 + j * 4);
        CP16(sb + PS_BL + d, BKl + kr * 64 + j * 4);
    }
    CP_COMMIT();

    float* cst = (float*)(dsm + PS_CONST);
    if (mode && tid < 64) {
        float mu  = g_stats[statsL * 256 + 128 + tid] * (1.f / NN);
        float var = g_stats[statsL * 256 + 192 + tid] * (1.f / NN) - mu * mu;
        float iv  = rsqrtf(fmaxf(var, 0.f) + EPS_BN);
        float s2  = iv * go[tid];
        cst[tid] = s2;
        cst[64 + tid] = bo[tid] - mu * s2;
    }
    __syncthreads();

    for (int i = tid; i < 2048; i += 256) {
        int row = i >> 4, c4 = (i & 15) * 4, gr = tB + row;
        float4 v = make_float4(0.f, 0.f, 0.f, 0.f);
        if (gr < NN) {
            float4 o = *(const float4*)(srcO + (size_t)gr * 64 + c4);
            if (mode) {
                float4 hp = *(const float4*)(hprev + (size_t)gr * 64 + c4);
                v.x = fmaxf(o.x * cst[c4 + 0] + cst[64 + c4 + 0], 0.f) + hp.x;
                v.y = fmaxf(o.y * cst[c4 + 1] + cst[64 + c4 + 1], 0.f) + hp.y;
                v.z = fmaxf(o.z * cst[c4 + 2] + cst[64 + c4 + 2], 0.f) + hp.z;
                v.w = fmaxf(o.w * cst[c4 + 3] + cst[64 + c4 + 3], 0.f) + hp.w;
                *(float4*)(h_out + (size_t)gr * 64 + c4) = v;
            } else {
                v = o;
            }
        }
        uint32_t uh0, ul0, uh1, ul1;
        split_pack(v.x, v.y, uh0, ul0);
        split_pack(v.z, v.w, uh1, ul1);
        int pi = gr * 32 + (c4 >> 1);
        *(uint2*)(g_hH + pi) = make_uint2(uh0, uh1);
        *(uint2*)(g_hL + pi) = make_uint2(ul0, ul1);
        uint32_t soff = (uint32_t)(row * 144 + c4 * 2);
        *(uint2*)(dsm + PS_AH + soff) = make_uint2(uh0, uh1);
        *(uint2*)(dsm + PS_AL + soff) = make_uint2(ul0, ul1);
    }
    CP_WAIT(0);
    __syncthreads();

    float c[64];
#pragma unroll
    for (int i = 0; i < 64; i++) c[i] = 0.f;

    uint32_t aAoff = (uint32_t)(w * 16 + (l & 15)) * 144 + (uint32_t)(l >> 4) * 16;
    uint32_t aBoff = (uint32_t)(l & 15) * 272 + (uint32_t)(l >> 4) * 16;
    uint32_t aAh = sb + PS_AH + aAoff, aAl = sb + PS_AL + aAoff;
    uint32_t aBh = sb + PS_BH + aBoff, aBl = sb + PS_BL + aBoff;
#pragma unroll
    for (int ks = 0; ks < 4; ks++) {
        uint32_t ah[4], al[4];
        ldsm4(ah, aAh + ks * 32);
        ldsm4(al, aAl + ks * 32);
#pragma unroll
        for (int nn = 0; nn < 8; nn++) {
            uint32_t bh[4], bl[4];
            ldsm4t(bh, aBh + ks * 16 * 272 + nn * 32);
            ldsm4t(bl, aBl + ks * 16 * 272 + nn * 32);
            mma16816(c + nn * 8,     ah, bh[0], bh[1]);
            mma16816(c + nn * 8 + 4, ah, bh[2], bh[3]);
            mma16816(c + nn * 8,     ah, bl[0], bl[1]);
            mma16816(c + nn * 8 + 4, ah, bl[2], bl[3]);
            mma16816(c + nn * 8,     al, bh[0], bh[1]);
            mma16816(c + nn * 8 + 4, al, bh[2], bh[3]);
        }
    }
    __syncthreads();

    float* stage = (float*)dsm;
    int r0 = w * 16 + g, r1 = r0 + 8;
#pragma unroll
    for (int jj = 0; jj < 16; jj++) {
        int col = jj * 8 + 2 * t;
        stage[r0 * 132 + col]     = c[jj * 4 + 0];
        stage[r0 * 132 + col + 1] = c[jj * 4 + 1];
        stage[r1 * 132 + col]     = c[jj * 4 + 2];
        stage[r1 * 132 + col + 1] = c[jj * 4 + 3];
    }
    __syncthreads();
    for (int i = tid; i < 4096; i += 256) {
        int row = i >> 5, c4 = (i & 31) * 4;
        float4 v = make_float4(stage[row * 132 + c4],     stage[row * 132 + c4 + 1],
                               stage[row * 132 + c4 + 2], stage[row * 132 + c4 + 3]);
        *(float4*)(g_PQ + (size_t)(tB + row) * 128 + c4) = v;
    }
}

// ======================= aggregation -> packed fp16 X (one warp per node) ================
__global__ __launch_bounds__(256) void agg_kernel(const float* __restrict__ bM)
{
    int v = blockIdx.x * 8 + (threadIdx.x >> 5);
    int lane = threadIdx.x & 31;
    if (v >= NN) return;
    int beg = g_rowptr[v], end = g_rowptr[v + 1];
    int c0 = 2 * lane;
    const float* qrow = g_PQ + (size_t)v * 128 + 64;
    float2 qv = *(const float2*)(qrow + c0);
    float2 bv = *(const float2*)(bM + c0);
    float base0 = qv.x + bv.x;
    float base1 = qv.y + bv.y;
    float s0 = 0.f, s1 = 0.f, q0 = 0.f, q1 = 0.f;
    float mx0 = -INFINITY, mx1 = -INFINITY, mn0 = INFINITY, mn1 = INFINITY;
#pragma unroll 4
    for (int p = beg; p < end; p++) {
        int s = g_srcsorted[p];
        float2 pv = *(const float2*)(g_PQ + (size_t)s * 128 + c0);
        float m0 = pv.x + base0;
        float m1 = pv.y + base1;
        s0 += m0; q0 += m0 * m0; mx0 = fmaxf(mx0, m0); mn0 = fminf(mn0, m0);
        s1 += m1; q1 += m1 * m1; mx1 = fmaxf(mx1, m1); mn1 = fminf(mn1, m1);
    }
    float deg = (float)(end - beg);
    float denom = fmaxf(deg, 1.f);
    float inv = 1.f / denom;
    float mean0 = s0 * inv, mean1 = s1 * inv;
    float var0 = fmaxf(q0 * inv - mean0 * mean0, 0.f);
    float var1 = fmaxf(q1 * inv - mean1 * mean1, 0.f);
    float std0 = sqrtf(var0 + 1e-30f);
    float std1 = sqrtf(var1 + 1e-30f);
    if (end == beg) { mx0 = mx1 = 0.f; mn0 = mn1 = 0.f; }
    uint32_t* xh = g_Xh + (size_t)v * 224;
    xh[lane]       = pack_h2(mean0, mean1);
    xh[32 + lane]  = pack_h2(mx0, mx1);
    xh[64 + lane]  = pack_h2(mn0, mn1);
    xh[96 + lane]  = pack_h2(std0, std1);
    xh[128 + lane] = pack_h2(var0, var1);
    xh[160 + lane] = pack_h2(s0, s1);
    {
        uint32_t hh_ = g_hH[(size_t)v * 32 + lane];
        uint32_t hl_ = g_hL[(size_t)v * 32 + lane];
        __nv_bfloat162 hb = *(__nv_bfloat162*)&hh_;
        __nv_bfloat162 lb = *(__nv_bfloat162*)&hl_;
        float h0 = __bfloat162float(hb.x) + __bfloat162float(lb.x);
        float h1 = __bfloat162float(hb.y) + __bfloat162float(lb.y);
        xh[192 + lane] = pack_h2(h0, h1);
    }
    if (lane == 0) {
        float logD = logf(deg + 1.f);
        g_scal[2 * v]     = logD * (1.f / DELTA_F);
        g_scal[2 * v + 1] = (logD > 0.f) ? (DELTA_F / logD) : 0.f;
    }
}

// ======================= Z MMA (fp16 2-pass) + fused combine -> packed hu + BN1 stats ====
// A = X fp16 single; B = Bz fp16 hi+lo (exact). Z = ah@bh + ah@bl.
#define ZS_A  0
#define ZS_BH 18432
#define ZS_BL 44032
#define Z_STAGE 69632
#define ZS_BU (2 * Z_STAGE)
#define Z_SMEM (2 * Z_STAGE + 256)

__global__ __launch_bounds__(256) void zmma_kernel(const float* __restrict__ bU, int layer)
{
    extern __shared__ char dsm[];
    uint32_t sb = smem_u32(dsm);
    int tid = threadIdx.x, w = tid >> 5, l = tid & 31, g = l >> 2, t = l & 3;
    int tB = blockIdx.x * 128;
    if (tid < 64) ((float*)(dsm + ZS_BU))[tid] = bU[tid];

    const uint32_t* BzH = g_BzKh + (size_t)layer * 43008;
    const uint32_t* BzL = g_BzKl + (size_t)layer * 43008;

    float c[96];
#pragma unroll
    for (int i = 0; i < 96; i++) c[i] = 0.f;

    uint32_t aAoff = (uint32_t)(w * 16 + (l & 15)) * 144 + (uint32_t)(l >> 4) * 16;
    uint32_t aBoff = (uint32_t)(l & 15) * 400 + (uint32_t)(l >> 4) * 16;

    // prefetch chunk 0
    {
        uint32_t bs = sb;
        for (int i = tid; i < 1024; i += 256) {
            int r = i >> 3, j = i & 7;
            CP16(bs + ZS_A + (uint32_t)(r * 144 + j * 16),
                 g_Xh + (size_t)(tB + r) * 224 + j * 4);
        }
        for (int i = tid; i < 1536; i += 256) {
            int kr = i / 24, j = i - kr * 24;
            uint32_t d = (uint32_t)(kr * 400 + j * 16);
            CP16(bs + ZS_BH + d, BzH + kr * 96 + j * 4);
            CP16(bs + ZS_BL + d, BzL + kr * 96 + j * 4);
        }
        CP_COMMIT();
    }

    for (int ch = 0; ch < 7; ch++) {
        if (ch < 6) {
            uint32_t bs = sb + ((ch + 1) & 1) * Z_STAGE;
            int kc = (ch + 1) * 32;
            const uint32_t* Bh = BzH + (size_t)(ch + 1) * 6144;
            const uint32_t* Bl = BzL + (size_t)(ch + 1) * 6144;
            for (int i = tid; i < 1024; i += 256) {
                int r = i >> 3, j = i & 7;
                CP16(bs + ZS_A + (uint32_t)(r * 144 + j * 16),
                     g_Xh + (size_t)(tB + r) * 224 + kc + j * 4);
            }
            for (int i = tid; i < 1536; i += 256) {
                int kr = i / 24, j = i - kr * 24;
                uint32_t d = (uint32_t)(kr * 400 + j * 16);
                CP16(bs + ZS_BH + d, Bh + kr * 96 + j * 4);
                CP16(bs + ZS_BL + d, Bl + kr * 96 + j * 4);
            }
            CP_COMMIT();
            CP_WAIT(1);
        } else {
            CP_WAIT(0);
        }
        __syncthreads();

        uint32_t bufOff = (ch & 1) * Z_STAGE;
        uint32_t aA = sb + bufOff + ZS_A + aAoff;
        uint32_t aBh = sb + bufOff + ZS_BH + aBoff, aBl = sb + bufOff + ZS_BL + aBoff;
#pragma unroll
        for (int ks = 0; ks < 4; ks++) {
            uint32_t ah[4];
            ldsm4(ah, aA + ks * 32);
#pragma unroll
            for (int nn = 0; nn < 12; nn++) {
                uint32_t bh[4], bl[4];
                ldsm4t(bh, aBh + ks * 16 * 400 + nn * 32);
                ldsm4t(bl, aBl + ks * 16 * 400 + nn * 32);
                mma16816h(c + nn * 8,     ah, bh[0], bh[1]);
                mma16816h(c + nn * 8 + 4, ah, bh[2], bh[3]);
                mma16816h(c + nn * 8,     ah, bl[0], bl[1]);
                mma16816h(c + nn * 8 + 4, ah, bl[2], bl[3]);
            }
        }
        __syncthreads();
    }

    // fused combine epilogue (thread-local: n8-tile jj at c[jj*4]; Z0=jj 0-7, Z1=8-15, Z2=16-23)
    int r0 = w * 16 + g, r1 = r0 + 8;
    int gr0 = tB + r0, gr1 = tB + r1;
    float amp0 = g_scal[2 * gr0], att0 = g_scal[2 * gr0 + 1];
    float amp1 = g_scal[2 * gr1], att1 = g_scal[2 * gr1 + 1];
    const float* buS = (const float*)(dsm + ZS_BU);
    float* stage = (float*)dsm;
#pragma unroll
    for (int jj = 0; jj < 8; jj++) {
        int col = jj * 8 + 2 * t;
        float b0v = buS[col], b1v = buS[col + 1];
        stage[r0 * 66 + col]     = (c[jj*4+0] + amp0 * c[(jj+8)*4+0] + att0 * c[(jj+16)*4+0] + b0v) * SNORM;
        stage[r0 * 66 + col + 1] = (c[jj*4+1] + amp0 * c[(jj+8)*4+1] + att0 * c[(jj+16)*4+1] + b1v) * SNORM;
        stage[r1 * 66 + col]     = (c[jj*4+2] + amp1 * c[(jj+8)*4+2] + att1 * c[(jj+16)*4+2] + b0v) * SNORM;
        stage[r1 * 66 + col + 1] = (c[jj*4+3] + amp1 * c[(jj+8)*4+3] + att1 * c[(jj+16)*4+3] + b1v) * SNORM;
    }
    __syncthreads();
    // packed hu store
    for (int i = tid; i < 2048; i += 256) {
        int row = i >> 4, c4 = (i & 15) * 4;
        float4 v = make_float4(stage[row * 66 + c4],     stage[row * 66 + c4 + 1],
                               stage[row * 66 + c4 + 2], stage[row * 66 + c4 + 3]);
        uint32_t uh0, ul0, uh1, ul1;
        split_pack(v.x, v.y, uh0, ul0);
        split_pack(v.z, v.w, uh1, ul1);
        int pi = (tB + row) * 32 + (c4 >> 1);
        *(uint2*)(g_huH + pi) = make_uint2(uh0, uh1);
        *(uint2*)(g_huL + pi) = make_uint2(ul0, ul1);
    }
    // BN1 stats
    {
        int ci = tid & 63, hh = tid >> 6;
        float s = 0.f, q = 0.f;
        for (int r = hh * 32; r < hh * 32 + 32; r++) {
            if (tB + r < NN) { float x = stage[r * 66 + ci]; s += x; q += x * x; }
        }
        atomicAdd(&g_stats[layer * 256 + ci], s);
        atomicAdd(&g_stats[layer * 256 + 64 + ci], q);
    }
}

// ======================= mix MMA: BN1-folded hu @ Wmix + leaky + residual + BN2 stats ====
#define MX_AH 0
#define MX_AL 18432
#define MX_BH 36864
#define MX_BL 46080
#define MX_CONST 55296
#define MX_SMEM 57088

__global__ __launch_bounds__(256) void mix_kernel(
    const float* __restrict__ h_in, const float* __restrict__ Wmix,
    const float* __restrict__ bmix, const float* __restrict__ gt,
    const float* __restrict__ bt, int layer)
{
    extern __shared__ char dsm[];
    uint32_t sb = smem_u32(dsm);
    int tid = threadIdx.x, w = tid >> 5, l = tid & 31, g = l >> 2, t = l & 3;
    int tB = blockIdx.x * 128;

    for (int i = tid; i < 1024; i += 256) {
        int r = i >> 3, j = i & 7;
        uint32_t d = (uint32_t)(r * 144 + j * 16);
        CP16(sb + MX_AH + d, g_huH + (size_t)(tB + r) * 32 + j * 4);
        CP16(sb + MX_AL + d, g_huL + (size_t)(tB + r) * 32 + j * 4);
    }
    CP_COMMIT();

    float* cst = (float*)(dsm + MX_CONST);
    if (tid < 64) {
        float mu  = g_stats[layer * 256 + tid] * (1.f / NN);
        float var = g_stats[layer * 256 + 64 + tid] * (1.f / NN) - mu * mu;
        float iv  = rsqrtf(fmaxf(var, 0.f) + EPS_BN);
        float s   = gt[tid] * iv;
        cst[tid] = s;
        cst[64 + tid] = bt[tid] - mu * s;
    }
    __syncthreads();

    for (int i = tid; i < 2048; i += 256) {
        int k = i >> 5, n2 = i & 31;
        float s = cst[k];
        float2 wv = *(const float2*)(Wmix + k * 64 + n2 * 2);
        uint32_t uh, ul; split_pack(s * wv.x, s * wv.y, uh, ul);
        uint32_t d = (uint32_t)(k * 144 + n2 * 4);
        *(uint32_t*)(dsm + MX_BH + d) = uh;
        *(uint32_t*)(dsm + MX_BL + d) = ul;
    }
    {
        int n = tid & 63, kq = tid >> 6;
        float pb = 0.f;
        for (int k = kq * 16; k < kq * 16 + 16; k++)
            pb += cst[64 + k] * Wmix[k * 64 + n];
        cst[192 + tid] = pb;
    }
    CP_WAIT(0);
    __syncthreads();
    if (tid < 64)
        cst[128 + tid] = bmix[tid] + cst[192 + tid] + cst[256 + tid] + cst[320 + tid] + cst[384 + tid];

    float c[32];
#pragma unroll
    for (int i = 0; i < 32; i++) c[i] = 0.f;

    uint32_t aAoff = (uint32_t)(w * 16 + (l & 15)) * 144 + (uint32_t)(l >> 4) * 16;
    uint32_t aBoff = (uint32_t)(l & 15) * 144 + (uint32_t)(l >> 4) * 16;
    uint32_t aAh = sb + MX_AH + aAoff, aAl = sb + MX_AL + aAoff;
    uint32_t aBh = sb + MX_BH + aBoff, aBl = sb + MX_BL + aBoff;
#pragma unroll
    for (int ks = 0; ks < 4; ks++) {
        uint32_t ah[4], al[4];
        ldsm4(ah, aAh + ks * 32);
        ldsm4(al, aAl + ks * 32);
#pragma unroll
        for (int nn = 0; nn < 4; nn++) {
            uint32_t bh[4], bl[4];
            ldsm4t(bh, aBh + ks * 16 * 144 + nn * 32);
            ldsm4t(bl, aBl + ks * 16 * 144 + nn * 32);
            mma16816(c + nn * 8,     ah, bh[0], bh[1]);
            mma16816(c + nn * 8 + 4, ah, bh[2], bh[3]);
            mma16816(c + nn * 8,     ah, bl[0], bl[1]);
            mma16816(c + nn * 8 + 4, ah, bl[2], bl[3]);
            mma16816(c + nn * 8,     al, bh[0], bh[1]);
            mma16816(c + nn * 8 + 4, al, bh[2], bh[3]);
        }
    }
    __syncthreads();

    float* stage = (float*)dsm;
    int r0 = w * 16 + g, r1 = r0 + 8;
    int gr0 = tB + r0, gr1 = tB + r1;
#pragma unroll
    for (int jj = 0; jj < 8; jj++) {
        int col = jj * 8 + 2 * t;
        float bb0 = cst[128 + col], bb1 = cst[128 + col + 1];
        float a0 = c[jj * 4 + 0] + bb0, a1 = c[jj * 4 + 1] + bb1;
        float a2 = c[jj * 4 + 2] + bb0, a3 = c[jj * 4 + 3] + bb1;
        a0 = (a0 > 0.f) ? a0 : 0.01f * a0;
        a1 = (a1 > 0.f) ? a1 : 0.01f * a1;
        a2 = (a2 > 0.f) ? a2 : 0.01f * a2;
        a3 = (a3 > 0.f) ? a3 : 0.01f * a3;
        float h0 = 0.f, h1 = 0.f, h2 = 0.f, h3 = 0.f;
        if (gr0 < NN) { float2 hv = *(const float2*)(h_in + (size_t)gr0 * 64 + col); h0 = hv.x; h1 = hv.y; }
        if (gr1 < NN) { float2 hv = *(const float2*)(h_in + (size_t)gr1 * 64 + col); h2 = hv.x; h3 = hv.y; }
        stage[r0 * 66 + col]     = a0 + h0;
        stage[r0 * 66 + col + 1] = a1 + h1;
        stage[r1 * 66 + col]     = a2 + h2;
        stage[r1 * 66 + col + 1] = a3 + h3;
    }
    __syncthreads();
    for (int i = tid; i < 2048; i += 256) {
        int row = i >> 4, c4 = (i & 15) * 4;
        int gr = tB + row;
        if (gr < NN) {
            float4 v = make_float4(stage[row * 66 + c4],     stage[row * 66 + c4 + 1],
                                   stage[row * 66 + c4 + 2], stage[row * 66 + c4 + 3]);
            *(float4*)(g_ot + (size_t)gr * 64 + c4) = v;
        }
    }
    {
        int ci = tid & 63, hh = tid >> 6;
        float s = 0.f, q = 0.f;
        for (int r = hh * 32; r < hh * 32 + 32; r++) {
            if (tB + r < NN) { float x = stage[r * 66 + ci]; s += x; q += x * x; }
        }
        atomicAdd(&g_stats[layer * 256 + 128 + ci], s);
        atomicAdd(&g_stats[layer * 256 + 192 + ci], q);
    }
}

// ======================= final (layer 3): BN2 + relu + residual -> d_out =================
__global__ void final_kernel(const float* __restrict__ h_in,
                             const float* __restrict__ go,
                             const float* __restrict__ bo,
                             float* __restrict__ h_out, int layer)
{
    int i = blockIdx.x * blockDim.x + threadIdx.x;
    if (i >= NN * 32) return;
    int p = i & 31;
    int c0 = 2 * p;
    float mu0  = g_stats[layer * 256 + 128 + c0] * (1.f / NN);
    float mu1  = g_stats[layer * 256 + 128 + c0 + 1] * (1.f / NN);
    float var0 = g_stats[layer * 256 + 192 + c0] * (1.f / NN) - mu0 * mu0;
    float var1 = g_stats[layer * 256 + 192 + c0 + 1] * (1.f / NN) - mu1 * mu1;
    float iv0  = rsqrtf(fmaxf(var0, 0.f) + EPS_BN);
    float iv1  = rsqrtf(fmaxf(var1, 0.f) + EPS_BN);
    float2 ot = *(const float2*)(g_ot + (size_t)i * 2);
    float2 hi = *(const float2*)(h_in + (size_t)i * 2);
    float v0 = fmaxf((ot.x - mu0) * iv0 * go[c0]     + bo[c0],     0.f) + hi.x;
    float v1 = fmaxf((ot.y - mu1) * iv1 * go[c0 + 1] + bo[c0 + 1], 0.f) + hi.y;
    *(float2*)(h_out + (size_t)i * 2) = make_float2(v0, v1);
}

// ======================= host =======================
extern "C" void kernel_launch(void* const* d_in, const int* in_sizes, int n_in,
                              void* d_out, int out_size)
{
    (void)in_sizes; (void)n_in; (void)out_size;
    const float* node_feat = (const float*)d_in[0];
    const int*   esrc = (const int*)d_in[2];
    const int*   edst = (const int*)d_in[3];
    const float* WM   = (const float*)d_in[4];
    const float* bM   = (const float*)d_in[5];
    const float* WU   = (const float*)d_in[6];
    const float* bU   = (const float*)d_in[7];
    const float* gt   = (const float*)d_in[8];
    const float* bt   = (const float*)d_in[9];
    const float* Wmix = (const float*)d_in[10];
    const float* bmix = (const float*)d_in[11];
    const float* go   = (const float*)d_in[12];
    const float* bo   = (const float*)d_in[13];
    float* out = (float*)d_out;

    cudaFuncSetAttribute(zmma_kernel, cudaFuncAttributeMaxDynamicSharedMemorySize, Z_SMEM);
    cudaFuncSetAttribute(pqmma_kernel, cudaFuncAttributeMaxDynamicSharedMemorySize, P_SMEM);
    cudaFuncSetAttribute(mix_kernel, cudaFuncAttributeMaxDynamicSharedMemorySize, MX_SMEM);

    float *phA, *phB, *pot;
    cudaGetSymbolAddress((void**)&phA, g_hA);
    cudaGetSymbolAddress((void**)&phB, g_hB);
    cudaGetSymbolAddress((void**)&pot, g_ot);

    // setup: prepack + CSR build; pqmma L0 slotted before scatter (no CSR dep)
    prepack_all_kernel<<<936, 256>>>(WM, WU);
    hist_kernel<<<(NE + 255) / 256, 256>>>(edst);
    scan_kernel<<<1, 1024>>>();
    pqmma_kernel<<<NTILES, 256, P_SMEM>>>(node_feat, node_feat, go, bo, phA, 0, 0, 0);
    scatter_kernel<<<(NE + 255) / 256, 256>>>(esrc, edst);

    // h chain: h0=node_feat, h1=phA, h2=phB, h3=phA
    const float* hptr[4] = { node_feat, phA, phB, phA };

    for (int lyr = 0; lyr < 4; lyr++) {
        if (lyr > 0)
            pqmma_kernel<<<NTILES, 256, P_SMEM>>>(pot, hptr[lyr - 1],
                                                  go + (lyr - 1) * 64, bo + (lyr - 1) * 64,
                                                  (float*)hptr[lyr], lyr - 1, lyr, 1);
        agg_kernel<<<(NN + 7) / 8, 256>>>(bM + lyr * 64);
        zmma_kernel<<<NTILES, 256, Z_SMEM>>>(bU + lyr * 64, lyr);
        mix_kernel<<<NTILES, 256, MX_SMEM>>>(hptr[lyr], Wmix + (size_t)lyr * 4096,
                                             bmix + lyr * 64, gt + lyr * 64,
                                             bt + lyr * 64, lyr);
    }
    final_kernel<<<(NN * 32 + 255) / 256, 256>>>(hptr[3], go + 3 * 64, bo + 3 * 64, out, 3);
}